// round 12
// baseline (speedup 1.0000x reference)
#include <cuda_runtime.h>
#include <cuda_fp16.h>
#include <cstdint>
#include <cstddef>

#define B_ 256
#define T_ 512
#define H_ 256
#define I_ 64
#define CSZ 8
#define MR 16
#define NLOC 128
#define TCH 32

// ---------------- device scratch ----------------
__device__ float  g_h2last[B_ * H_];
__device__ __half g_whh0[CSZ * NLOC * 256];    // L0 recurrent weights, rank-sliced
__device__ __half g_w1cat[CSZ * NLOC * 512];   // L1 [Whh1|Wih1] rows, rank-sliced
__device__ __half g_wih0[CSZ * NLOC * 64];
__device__ float  g_bias0[CSZ * NLOC];
__device__ float  g_bias1[CSZ * NLOC];
// Precomputed L0 input-gate terms (bias folded): [cta(128), t(512), tid(256), 8]
__device__ float  g_xg0[(size_t)128 * 512 * 256 * 8];

// ---------------- helpers ----------------
__device__ __forceinline__ unsigned su32(const void* p) {
    unsigned a;
    asm("{ .reg .u64 t; cvta.to.shared.u64 t, %1; cvt.u32.u64 %0, t; }" : "=r"(a) : "l"(p));
    return a;
}
__device__ __forceinline__ float tanhap(float x) {
    float y;
    asm("tanh.approx.f32 %0, %1;" : "=f"(y) : "f"(x));
    return y;
}
__device__ __forceinline__ float sigm(float x) {
    return fmaf(tanhap(0.5f * x), 0.5f, 0.5f);
}
__device__ __forceinline__ void ldsm_x2(uint32_t& b0, uint32_t& b1, unsigned a) {
    asm volatile("ldmatrix.sync.aligned.m8n8.x2.shared.b16 {%0,%1}, [%2];"
                 : "=r"(b0), "=r"(b1) : "r"(a));
}
__device__ __forceinline__ void ldsm_x4(uint32_t* r, unsigned a) {
    asm volatile("ldmatrix.sync.aligned.m8n8.x4.shared.b16 {%0,%1,%2,%3}, [%4];"
                 : "=r"(r[0]), "=r"(r[1]), "=r"(r[2]), "=r"(r[3]) : "r"(a));
}
__device__ __forceinline__ void mma16816(float* acc, const uint32_t* a, uint32_t b0, uint32_t b1) {
    asm volatile(
        "mma.sync.aligned.m16n8k16.row.col.f32.f16.f16.f32 "
        "{%0,%1,%2,%3}, {%4,%5,%6,%7}, {%8,%9}, {%0,%1,%2,%3};"
        : "+f"(acc[0]), "+f"(acc[1]), "+f"(acc[2]), "+f"(acc[3])
        : "r"(a[0]), "r"(a[1]), "r"(a[2]), "r"(a[3]), "r"(b0), "r"(b1));
}

// ---------------- weight prep ----------------
// Local row l of rank r: gate g = l>>5, h-col = r*32 + (l&31), grow = g*256 + r*32 + (l&31).
__global__ void prep_kernel(const float* __restrict__ Wih0, const float* __restrict__ Whh0,
                            const float* __restrict__ bih0, const float* __restrict__ bhh0,
                            const float* __restrict__ Wih1, const float* __restrict__ Whh1,
                            const float* __restrict__ bih1, const float* __restrict__ bhh1) {
    int blk = blockIdx.x;
    int li = blk & 1023;
    int r = li >> 7, l = li & 127;
    int grow = (l >> 5) * H_ + r * 32 + (l & 31);
    if (blk < 1024) {
        for (int k = threadIdx.x; k < 256; k += blockDim.x)
            g_whh0[(r * NLOC + l) * 256 + k] = __float2half_rn(Whh0[grow * H_ + k]);
        for (int k = threadIdx.x; k < 64; k += blockDim.x)
            g_wih0[(r * NLOC + l) * 64 + k] = __float2half_rn(Wih0[grow * I_ + k]);
        if (threadIdx.x == 0) g_bias0[r * NLOC + l] = bih0[grow] + bhh0[grow];
    } else {
        for (int k = threadIdx.x; k < 512; k += blockDim.x) {
            float v = (k < 256) ? Whh1[grow * H_ + k] : Wih1[grow * H_ + (k - 256)];
            g_w1cat[(r * NLOC + l) * 512 + k] = __float2half_rn(v);
        }
        if (threadIdx.x == 0) g_bias1[r * NLOC + l] = bih1[grow] + bhh1[grow];
    }
}

// ---------------- time-parallel L0 input GEMM: xg0[cta,t,tid,0:8] ----------------
__global__ void __launch_bounds__(256) xg_gemm64(const float* __restrict__ xin) {
    constexpr int KT  = 4;
    constexpr int KPB = (64 + 8) * 2;   // 144

    extern __shared__ __align__(16) char smem[];
    char*  sW    = smem;
    char*  sB    = sW + NLOC * KPB;
    float* sG    = (float*)(sB + MR * KPB);
    float* sBias = sG + NLOC * 17;

    const int tid  = threadIdx.x;
    const int wid  = tid >> 5;
    const int lane = tid & 31;
    const int rank = blockIdx.x & 7;
    const int bm0  = (blockIdx.x >> 3) * MR;
    const int t0   = blockIdx.y * TCH;

    {
        const uint4* src = (const uint4*)(g_wih0 + (size_t)rank * NLOC * 64);
        for (int i = tid; i < NLOC * 8; i += 256) {
            int l = i >> 3, c = i & 7;
            *(uint4*)(sW + l * KPB + c * 16) = src[i];
        }
    }
    if (tid < NLOC) sBias[tid] = g_bias0[rank * NLOC + tid];
    __syncthreads();

    uint32_t wreg[KT][4];
    {
        unsigned rb = su32(sW) + (unsigned)(wid * 16 + (lane & 15)) * KPB + ((lane & 16) ? 16u : 0u);
#pragma unroll
        for (int kt = 0; kt < KT; kt++) ldsm_x4(wreg[kt], rb + kt * 32);
    }

    const unsigned sBu = su32(sB);
    const unsigned boffL = (unsigned)((lane & 7) * KPB) + ((lane & 8) ? 16u : 0u);
    const int gid = lane >> 2, ctid = lane & 3;
    const int m_act = tid >> 4, jj = tid & 15;
    const int mx = tid >> 4, cx = tid & 15;

    for (int tt = 0; tt < TCH; tt++) {
        const int t = t0 + tt;
        float4 v = *(const float4*)&xin[((size_t)(bm0 + mx) * T_ + t) * I_ + cx * 4];
        __half2* d = (__half2*)(sB + mx * KPB + cx * 8);
        d[0] = __floats2half2_rn(v.x, v.y);
        d[1] = __floats2half2_rn(v.z, v.w);
        __syncthreads();

        float accA[2][4] = {{0.f,0.f,0.f,0.f},{0.f,0.f,0.f,0.f}};
#pragma unroll
        for (int nt = 0; nt < 2; nt++) {
            unsigned bb = sBu + (unsigned)(nt * 8) * KPB + boffL;
#pragma unroll
            for (int kt = 0; kt < KT; kt++) {
                uint32_t b0, b1;
                ldsm_x2(b0, b1, bb + kt * 32);
                mma16816(accA[nt], wreg[kt], b0, b1);
            }
        }
#pragma unroll
        for (int nt = 0; nt < 2; nt++) {
            int col = nt * 8 + 2 * ctid;
            int row = wid * 16 + gid;
            sG[row * 17 + col]           = accA[nt][0];
            sG[row * 17 + col + 1]       = accA[nt][1];
            sG[(row + 8) * 17 + col]     = accA[nt][2];
            sG[(row + 8) * 17 + col + 1] = accA[nt][3];
        }
        __syncthreads();
        {
            int j0 = 2 * jj, j1 = j0 + 1;
            float4 oA, oB;
            oA.x = sG[(0  + j0) * 17 + m_act] + sBias[0  + j0];
            oA.y = sG[(0  + j1) * 17 + m_act] + sBias[0  + j1];
            oA.z = sG[(32 + j0) * 17 + m_act] + sBias[32 + j0];
            oA.w = sG[(32 + j1) * 17 + m_act] + sBias[32 + j1];
            oB.x = sG[(64 + j0) * 17 + m_act] + sBias[64 + j0];
            oB.y = sG[(64 + j1) * 17 + m_act] + sBias[64 + j1];
            oB.z = sG[(96 + j0) * 17 + m_act] + sBias[96 + j0];
            oB.w = sG[(96 + j1) * 17 + m_act] + sBias[96 + j1];
            size_t base = (((size_t)blockIdx.x * T_ + t) * 256 + tid) * 8;
            *(float4*)&g_xg0[base]     = oA;
            *(float4*)&g_xg0[base + 4] = oB;
        }
        __syncthreads();
    }
}

// ---------------- fused 2-layer wavefront loop, 512 threads, k-split warp pairs ----
// Cluster of 8 CTAs = one batch group (16 rows). 16 warps: wm = wid&7 selects the
// M-block (16 gate rows), wg = wid>>3 selects the K-half.
//   GEMM1 (W1cat, regs): warp handles kt wg*16..wg*16+15 of 32   -> partials sG1a/sG1b
//   GEMM0 (Whh0, SMEM A reload): kt wg*8..wg*8+7 of 16           -> partials sG0a/sG0b
// Cell phase: warps 0-7 run cell0 (+h0 publish), warps 8-15 run cell1 (+h1 publish).
__global__ void __launch_bounds__(512, 1) __cluster_dims__(CSZ, 1, 1)
lstm_fused() {
    constexpr int W1B  = 1040;                   // 520-half row stride (W1cat stage, hcat)
    constexpr int HCB  = MR * W1B;               // 16640
    constexpr int WHH0B = 528;                   // Whh0 persistent row stride bytes
    constexpr int STG1_OFF = NLOC * WHH0B;       // 67584 (W1cat staging, init-only)
    constexpr int HC_OFF   = STG1_OFF;           // runtime hcat overlays dead staging
    constexpr int SG0A_OFF = HC_OFF + 2 * HCB;   // 100864
    constexpr int SG0B_OFF = SG0A_OFF + NLOC * 17 * 4;
    constexpr int SG1A_OFF = SG0B_OFF + NLOC * 17 * 4;
    constexpr int SG1B_OFF = SG1A_OFF + NLOC * 17 * 4;
    constexpr int SB1_OFF  = SG1B_OFF + NLOC * 17 * 4;   // 135680

    extern __shared__ __align__(16) char smem[];
    char*  sHC  = smem + HC_OFF;
    float* sG0a = (float*)(smem + SG0A_OFF);
    float* sG0b = (float*)(smem + SG0B_OFF);
    float* sG1a = (float*)(smem + SG1A_OFF);
    float* sG1b = (float*)(smem + SG1B_OFF);
    float* sB1  = (float*)(smem + SB1_OFF);

    const int tid  = threadIdx.x;
    const int wid  = tid >> 5;
    const int lane = tid & 31;
    const int wg   = wid >> 3;       // K-half / cell role
    const int wm   = wid & 7;        // M-block
    unsigned rank;
    asm("mov.u32 %0, %%cluster_ctarank;" : "=r"(rank));
    const int bm0 = (blockIdx.x >> 3) * MR;

    // ---- init: stage Whh0 (persistent, [0,67584)) and W1cat (staging) in parallel ----
    {
        const uint4* s0 = (const uint4*)(g_whh0 + (size_t)rank * NLOC * 256);
        for (int i = tid; i < NLOC * 32; i += 512) {
            int l = i >> 5, c = i & 31;
            *(uint4*)(smem + l * WHH0B + c * 16) = s0[i];
        }
        const uint4* s1 = (const uint4*)(g_w1cat + (size_t)rank * NLOC * 512);
        for (int i = tid; i < NLOC * 64; i += 512) {
            int l = i >> 6, c = i & 63;
            *(uint4*)(smem + STG1_OFF + l * W1B + c * 16) = s1[i];
        }
    }
    __syncthreads();

    // ---- wreg1: this warp's 16 k-tiles of W1cat ----
    uint32_t wreg1[16][4];
    {
        unsigned rb = su32(smem) + STG1_OFF
                    + (unsigned)(wm * 16 + (lane & 15)) * W1B + ((lane & 16) ? 16u : 0u)
                    + (unsigned)(wg * 16) * 32;
#pragma unroll
        for (int ktl = 0; ktl < 16; ktl++) ldsm_x4(wreg1[ktl], rb + ktl * 32);
    }
    __syncthreads();

    // ---- zero hcat buffers (overlays dead staging), load bias ----
    for (int i = tid; i < 2 * HCB / 4; i += 512) ((unsigned*)sHC)[i] = 0u;
    if (tid < NLOC) sB1[tid] = g_bias1[rank * NLOC + tid];

    const unsigned sHCu  = su32(sHC);
    const unsigned hoffL = (unsigned)((lane & 7) * W1B) + ((lane & 8) ? 16u : 0u);
    // per-superstep Whh0 A-frag reload base (persistent region at smem[0])
    const unsigned aw0 = su32(smem)
                       + (unsigned)(wm * 16 + (lane & 15)) * WHH0B + ((lane & 16) ? 16u : 0u)
                       + (unsigned)(wg * 8) * 32;
    const int gid = lane >> 2, ctid = lane & 3;
    const int ct = tid & 255;
    const int m_act = ct >> 4, jj = ct & 15;

    // publish slot: wg==0 -> h0 slot (+512), wg==1 -> h1 slot (+0)
    const unsigned poff = sHCu + (unsigned)(m_act * W1B + (wg ? 0 : 512) + (rank * 32 + 2 * jj) * 2);

    // xg0 stream (cell0 warps only)
    const float4* xg4 = (const float4*)g_xg0;
    const size_t xbase = ((size_t)blockIdx.x * T_) * 512 + ct * 2;
    float4 xgA, xgB;
    if (wg == 0) { xgA = xg4[xbase]; xgB = xg4[xbase + 1]; }

    float cA = 0.f, cB = 0.f;   // cell state (c of this thread's two h-cols, layer wg)

    __syncthreads();
    asm volatile("barrier.cluster.arrive.aligned;" ::: "memory");
    asm volatile("barrier.cluster.wait.aligned;" ::: "memory");

#pragma unroll 1
    for (int s = 0; s <= T_; s++) {
        const unsigned rb16 = (unsigned)((s & 1) * HCB);
        const unsigned wb16 = rb16 ^ (unsigned)HCB;
        const bool do0 = (s < T_);
        const bool do1 = (s >= 1);

        // prefetch xg[s+1]
        float4 pA, pB;
        if (wg == 0 && do0) {
            int tn = (s + 1 < T_) ? s + 1 : s;
            pA = xg4[xbase + (size_t)tn * 512];
            pB = xg4[xbase + (size_t)tn * 512 + 1];
        }

        // ---- GEMM1 partials: W1cat kt wg*16..+15 over hcat [h1|h0] ----
        {
            const unsigned kb = (unsigned)(wg * 16) * 32;
#pragma unroll
            for (int nt = 0; nt < 2; nt++) {
                float a1e[4] = {0,0,0,0}, a1o[4] = {0,0,0,0};
                unsigned hb = sHCu + rb16 + hoffL + (unsigned)(nt * 8) * W1B + kb;
#pragma unroll
                for (int ktl = 0; ktl < 16; ktl++) {
                    uint32_t b0, b1;
                    ldsm_x2(b0, b1, hb + ktl * 32);
                    mma16816((ktl & 1) ? a1o : a1e, wreg1[ktl], b0, b1);
                }
                int col = nt * 8 + 2 * ctid;
                int row = wm * 16 + gid;
                float* d = wg ? sG1b : sG1a;
                d[row * 17 + col]           = a1e[0] + a1o[0];
                d[row * 17 + col + 1]       = a1e[1] + a1o[1];
                d[(row + 8) * 17 + col]     = a1e[2] + a1o[2];
                d[(row + 8) * 17 + col + 1] = a1e[3] + a1o[3];
            }
        }

        // ---- GEMM0 partials: Whh0 kt wg*8..+7 (A reloaded from SMEM) over h0 slot ----
        {
            float a0[2][4] = {{0,0,0,0},{0,0,0,0}};
            const unsigned bb = sHCu + rb16 + hoffL + 512u + (unsigned)(wg * 8) * 32;
#pragma unroll
            for (int ktl = 0; ktl < 8; ktl++) {
                uint32_t a[4];
                ldsm_x4(a, aw0 + ktl * 32);
#pragma unroll
                for (int nt = 0; nt < 2; nt++) {
                    uint32_t b0, b1;
                    ldsm_x2(b0, b1, bb + (unsigned)(nt * 8) * W1B + ktl * 32);
                    mma16816(a0[nt], a, b0, b1);
                }
            }
#pragma unroll
            for (int nt = 0; nt < 2; nt++) {
                int col = nt * 8 + 2 * ctid;
                int row = wm * 16 + gid;
                float* d = wg ? sG0b : sG0a;
                d[row * 17 + col]           = a0[nt][0];
                d[row * 17 + col + 1]       = a0[nt][1];
                d[(row + 8) * 17 + col]     = a0[nt][2];
                d[(row + 8) * 17 + col + 1] = a0[nt][3];
            }
        }
        __syncthreads();

        const int j0 = 2 * jj, j1 = j0 + 1;

        if (wg == 0) {
            // ---- cell0 + h0 publish ----
            if (do0) {
                float gi0 = xgA.x + sG0a[(0  + j0) * 17 + m_act] + sG0b[(0  + j0) * 17 + m_act];
                float gi1 = xgA.y + sG0a[(0  + j1) * 17 + m_act] + sG0b[(0  + j1) * 17 + m_act];
                float gf0 = xgA.z + sG0a[(32 + j0) * 17 + m_act] + sG0b[(32 + j0) * 17 + m_act];
                float gf1 = xgA.w + sG0a[(32 + j1) * 17 + m_act] + sG0b[(32 + j1) * 17 + m_act];
                float gg0 = xgB.x + sG0a[(64 + j0) * 17 + m_act] + sG0b[(64 + j0) * 17 + m_act];
                float gg1 = xgB.y + sG0a[(64 + j1) * 17 + m_act] + sG0b[(64 + j1) * 17 + m_act];
                float go0 = xgB.z + sG0a[(96 + j0) * 17 + m_act] + sG0b[(96 + j0) * 17 + m_act];
                float go1 = xgB.w + sG0a[(96 + j1) * 17 + m_act] + sG0b[(96 + j1) * 17 + m_act];
                cA = sigm(gf0) * cA + sigm(gi0) * tanhap(gg0);
                float h0 = sigm(go0) * tanhap(cA);
                cB = sigm(gf1) * cB + sigm(gi1) * tanhap(gg1);
                float h1 = sigm(go1) * tanhap(cB);
                __half2 hp = __floats2half2_rn(h0, h1);
                unsigned hv = *(unsigned*)&hp;
                const unsigned src_ = poff + wb16;
#pragma unroll
                for (int rr = 0; rr < CSZ; rr++) {
                    unsigned ra;
                    asm volatile("mapa.shared::cluster.u32 %0, %1, %2;" : "=r"(ra) : "r"(src_), "r"(rr));
                    asm volatile("st.shared::cluster.u32 [%0], %1;" :: "r"(ra), "r"(hv) : "memory");
                }
                xgA = pA; xgB = pB;
            }
        } else {
            // ---- cell1 + h1 publish (or final output) ----
            if (do1) {
                float gi0 = sG1a[(0  + j0) * 17 + m_act] + sG1b[(0  + j0) * 17 + m_act] + sB1[0  + j0];
                float gi1 = sG1a[(0  + j1) * 17 + m_act] + sG1b[(0  + j1) * 17 + m_act] + sB1[0  + j1];
                float gf0 = sG1a[(32 + j0) * 17 + m_act] + sG1b[(32 + j0) * 17 + m_act] + sB1[32 + j0];
                float gf1 = sG1a[(32 + j1) * 17 + m_act] + sG1b[(32 + j1) * 17 + m_act] + sB1[32 + j1];
                float gg0 = sG1a[(64 + j0) * 17 + m_act] + sG1b[(64 + j0) * 17 + m_act] + sB1[64 + j0];
                float gg1 = sG1a[(64 + j1) * 17 + m_act] + sG1b[(64 + j1) * 17 + m_act] + sB1[64 + j1];
                float go0 = sG1a[(96 + j0) * 17 + m_act] + sG1b[(96 + j0) * 17 + m_act] + sB1[96 + j0];
                float go1 = sG1a[(96 + j1) * 17 + m_act] + sG1b[(96 + j1) * 17 + m_act] + sB1[96 + j1];
                cA = sigm(gf0) * cA + sigm(gi0) * tanhap(gg0);
                float h0 = sigm(go0) * tanhap(cA);
                cB = sigm(gf1) * cB + sigm(gi1) * tanhap(gg1);
                float h1 = sigm(go1) * tanhap(cB);
                if (s < T_) {
                    __half2 hp = __floats2half2_rn(h0, h1);
                    unsigned hv = *(unsigned*)&hp;
                    const unsigned src_ = poff + wb16;
#pragma unroll
                    for (int rr = 0; rr < CSZ; rr++) {
                        unsigned ra;
                        asm volatile("mapa.shared::cluster.u32 %0, %1, %2;" : "=r"(ra) : "r"(src_), "r"(rr));
                        asm volatile("st.shared::cluster.u32 [%0], %1;" :: "r"(ra), "r"(hv) : "memory");
                    }
                } else {
                    g_h2last[(bm0 + m_act) * H_ + rank * 32 + j0] = h0;
                    g_h2last[(bm0 + m_act) * H_ + rank * 32 + j1] = h1;
                }
            }
        }

        if (s < T_) {
            asm volatile("barrier.cluster.arrive.aligned;" ::: "memory");
            asm volatile("barrier.cluster.wait.aligned;" ::: "memory");
        }
    }
}

// ---------------- FC head ----------------
__global__ void head_kernel(const float* __restrict__ W1, const float* __restrict__ b1,
                            const float* __restrict__ W2, const float* __restrict__ b2,
                            float* __restrict__ out) {
    __shared__ float sLast[4][H_];
    __shared__ float sZ[4][5 * H_ + 4];
    int b0 = blockIdx.x * 4, tid = threadIdx.x;
#pragma unroll
    for (int i = 0; i < 4; i++) sLast[i][tid] = g_h2last[(b0 + i) * H_ + tid];
    __syncthreads();
#pragma unroll
    for (int q = 0; q < 5; q++) {
        int j = q * 256 + tid;
        const float* wr = W1 + (size_t)j * H_;
        float a0 = 0.f, a1 = 0.f, a2 = 0.f, a3 = 0.f;
#pragma unroll 8
        for (int k = 0; k < H_; k += 4) {
            float4 w = *(const float4*)&wr[k];
            a0 += w.x * sLast[0][k] + w.y * sLast[0][k+1] + w.z * sLast[0][k+2] + w.w * sLast[0][k+3];
            a1 += w.x * sLast[1][k] + w.y * sLast[1][k+1] + w.z * sLast[1][k+2] + w.w * sLast[1][k+3];
            a2 += w.x * sLast[2][k] + w.y * sLast[2][k+1] + w.z * sLast[2][k+2] + w.w * sLast[2][k+3];
            a3 += w.x * sLast[3][k] + w.y * sLast[3][k+1] + w.z * sLast[3][k+2] + w.w * sLast[3][k+3];
        }
        float bb = b1[j];
        sZ[0][j] = a0 + bb; sZ[1][j] = a1 + bb; sZ[2][j] = a2 + bb; sZ[3][j] = a3 + bb;
    }
    __syncthreads();
    int w = tid >> 5, l = tid & 31;
#pragma unroll
    for (int pp = 0; pp < 2; pp++) {
        int p = w + pp * 8;
        int b = p >> 2, o = p & 3;
        float acc = 0.f;
        for (int i = l; i < 1280; i += 32) acc += sZ[b][i] * W2[o * 1280 + i];
#pragma unroll
        for (int s = 16; s; s >>= 1) acc += __shfl_xor_sync(0xffffffffu, acc, s);
        if (l == 0) out[(b0 + b) * 4 + o] = acc + b2[o];
    }
}

// ---------------- launch ----------------
extern "C" void kernel_launch(void* const* d_in, const int* in_sizes, int n_in,
                              void* d_out, int out_size) {
    const float* x    = (const float*)d_in[0];
    const float* Wih0 = (const float*)d_in[1];
    const float* Whh0 = (const float*)d_in[2];
    const float* bih0 = (const float*)d_in[3];
    const float* bhh0 = (const float*)d_in[4];
    const float* Wih1 = (const float*)d_in[5];
    const float* Whh1 = (const float*)d_in[6];
    const float* bih1 = (const float*)d_in[7];
    const float* bhh1 = (const float*)d_in[8];
    const float* W1   = (const float*)d_in[9];
    const float* b1   = (const float*)d_in[10];
    const float* W2   = (const float*)d_in[11];
    const float* b2   = (const float*)d_in[12];

    constexpr int SMG = NLOC * 144 + MR * 144 + (NLOC * 17 + NLOC) * 4;   // 29952
    constexpr int SMF = 128 * 528 + 128 * 1040;   // 200704 (staging peak; runtime fits inside)

    cudaFuncSetAttribute(xg_gemm64, cudaFuncAttributeMaxDynamicSharedMemorySize, SMG);
    cudaFuncSetAttribute(lstm_fused, cudaFuncAttributeMaxDynamicSharedMemorySize, SMF);

    prep_kernel<<<2048, 64>>>(Wih0, Whh0, bih0, bhh0, Wih1, Whh1, bih1, bhh1);
    xg_gemm64<<<dim3(128, T_ / TCH), 256, SMG>>>(x);
    lstm_fused<<<128, 512, SMF>>>();
    head_kernel<<<64, 256>>>(W1, b1, W2, b2, (float*)d_out);
}